// round 9
// baseline (speedup 1.0000x reference)
#include <cuda_runtime.h>
#include <math.h>

#define IN_DIM   128
#define OUT_DIM  64
#define N_MAX    50000
#define E_MAX    800000
#define ALPHA    0.2f
#define EPS_ATT  1e-10f

// ---------------- scratch (no allocations allowed) ----------------
__device__ __align__(16) float g_h[N_MAX * OUT_DIM];  // projected features
__device__ float g_ssrc[N_MAX];             // h @ a[:64]
__device__ float g_stgt[N_MAX];             // h @ a[64:]
__device__ int   g_cnt[N_MAX];              // per-target degree (self-cleaning)
__device__ int   g_ptr[N_MAX + 1];          // CSR row offsets
__device__ int   g_ptrw[N_MAX];             // working cursor for reorder
__device__ int   g_src_sorted[E_MAX];       // src, sorted by target
__device__ float g_ex[E_MAX];               // exp(score), sorted by target

// ---------------- kernels ----------------

// GEMM: h = X @ W^T, fused with ssrc/stgt epilogue.
// 128 threads/block, tile = 32 rows x 64 cols, each thread computes 4x4.
__global__ __launch_bounds__(128) void gemm_kernel(
    const float* X, const float* W, const float* a, int n)
{
    __shared__ float4 Xs[32 * 32];
    __shared__ float4 Ws[64 * 32];

    int tid = threadIdx.x;
    for (int g = tid; g < 64 * 32; g += 128) {
        int c = g >> 5, kc = g & 31;
        Ws[(c << 5) | (kc ^ ((c >> 2) & 7))] = ((const float4*)W)[g];
    }
    int rowbase = blockIdx.x * 32;
    for (int g = tid; g < 32 * 32; g += 128) {
        int r = g >> 5, kc = g & 31;
        int row = rowbase + r;
        Xs[g] = (row < n) ? ((const float4*)X)[row * 32 + kc]
                          : make_float4(0.f, 0.f, 0.f, 0.f);
    }
    __syncthreads();

    int cg = tid & 15, rg = tid >> 4;
    int c0 = cg << 2, r0 = rg << 2;
    int swz = cg & 7;

    float acc[4][4] = {};
#pragma unroll 4
    for (int kc = 0; kc < 32; kc++) {
        float4 xv[4], wv[4];
#pragma unroll
        for (int j = 0; j < 4; j++)  xv[j] = Xs[((r0 + j) << 5) | kc];
#pragma unroll
        for (int jj = 0; jj < 4; jj++) wv[jj] = Ws[((c0 + jj) << 5) | (kc ^ swz)];
#pragma unroll
        for (int j = 0; j < 4; j++)
#pragma unroll
            for (int jj = 0; jj < 4; jj++)
                acc[j][jj] += xv[j].x * wv[jj].x + xv[j].y * wv[jj].y
                            + xv[j].z * wv[jj].z + xv[j].w * wv[jj].w;
    }

    float4 alo = ((const float4*)a)[cg];
    float4 ahi = ((const float4*)a)[16 + cg];

#pragma unroll
    for (int j = 0; j < 4; j++) {
        int row = rowbase + r0 + j;
        if (row < n) {
            float4 hv = make_float4(acc[j][0], acc[j][1], acc[j][2], acc[j][3]);
            *reinterpret_cast<float4*>(&g_h[row * OUT_DIM + c0]) = hv;
        }
        float p1 = acc[j][0]*alo.x + acc[j][1]*alo.y + acc[j][2]*alo.z + acc[j][3]*alo.w;
        float p2 = acc[j][0]*ahi.x + acc[j][1]*ahi.y + acc[j][2]*ahi.z + acc[j][3]*ahi.w;
#pragma unroll
        for (int off = 8; off; off >>= 1) {
            p1 += __shfl_down_sync(0xffffffffu, p1, off);
            p2 += __shfl_down_sync(0xffffffffu, p2, off);
        }
        if (cg == 0) {
            int row2 = rowbase + r0 + j;
            if (row2 < n) { g_ssrc[row2] = p1; g_stgt[row2] = p2; }
        }
    }
}

// CSR build 1: per-target degree histogram (g_cnt zeroed by aggregate_kernel
// of the previous invocation / zero static-init on the first).
__global__ void hist_kernel(const int* ei, int e) {
    int i = blockIdx.x * blockDim.x + threadIdx.x;
    if (i >= e) return;
    atomicAdd(&g_cnt[ei[e + i]], 1);
}

// CSR build 2: single-block exclusive scan over n counts -> g_ptr, g_ptrw.
__global__ __launch_bounds__(1024) void scan_kernel(int n, int e) {
    __shared__ int ssum[1024];
    int tid = threadIdx.x;
    int chunk = (n + 1023) / 1024;
    int beg = tid * chunk;
    int end = beg + chunk; if (end > n) end = n;
    int s = 0;
    for (int j = beg; j < end; j++) s += g_cnt[j];
    ssum[tid] = s;
    __syncthreads();
    // Hillis-Steele inclusive scan
    for (int off = 1; off < 1024; off <<= 1) {
        int t = (tid >= off) ? ssum[tid - off] : 0;
        __syncthreads();
        ssum[tid] += t;
        __syncthreads();
    }
    int run = ssum[tid] - s;     // exclusive offset for this chunk
    for (int j = beg; j < end; j++) {
        int c = g_cnt[j];
        g_ptr[j] = run;
        g_ptrw[j] = run;
        run += c;
    }
    if (tid == 0) g_ptr[n] = e;
}

// CSR build 3: scatter edges into target-sorted order; compute
// exp(leaky_relu(score)) once per edge here. No max-subtraction: scores are
// bounded ~[-20,20] for this input distribution, fp32 exp is safe and the
// softmax ratio is mathematically identical.
__global__ void reorder_kernel(const int* ei, int e) {
    int i = blockIdx.x * blockDim.x + threadIdx.x;
    if (i >= e) return;
    int s = ei[i];
    int t = ei[e + i];
    float v = g_ssrc[s] + g_stgt[t];
    v = (v > 0.0f) ? v : ALPHA * v;
    float ex = __expf(v);
    int pos = atomicAdd(&g_ptrw[t], 1);
    g_src_sorted[pos] = s;
    g_ex[pos] = ex;
}

// Aggregation: one warp per target node. Lanes own 2 output cols (float2).
// Register accumulation (no atomics), normalize + ELU + direct store to out.
// Also self-cleans g_cnt for the next invocation.
__global__ __launch_bounds__(256) void aggregate_kernel(float* out, int n) {
    int w = (blockIdx.x * blockDim.x + threadIdx.x) >> 5;
    int lane = threadIdx.x & 31;
    if (w >= n) return;
    int beg = g_ptr[w], end = g_ptr[w + 1];
    float ax = 0.f, ay = 0.f, es = 0.f;
    int k = beg;
    for (; k + 1 < end; k += 2) {
        int s0 = g_src_sorted[k], s1 = g_src_sorted[k + 1];
        float e0 = g_ex[k], e1 = g_ex[k + 1];
        float2 h0 = *reinterpret_cast<const float2*>(&g_h[s0 * OUT_DIM + (lane << 1)]);
        float2 h1 = *reinterpret_cast<const float2*>(&g_h[s1 * OUT_DIM + (lane << 1)]);
        es += e0 + e1;
        ax += e0 * h0.x + e1 * h1.x;
        ay += e0 * h0.y + e1 * h1.y;
    }
    if (k < end) {
        int s0 = g_src_sorted[k];
        float e0 = g_ex[k];
        float2 h0 = *reinterpret_cast<const float2*>(&g_h[s0 * OUT_DIM + (lane << 1)]);
        es += e0; ax += e0 * h0.x; ay += e0 * h0.y;
    }
    float inv = __fdividef(1.0f, es + EPS_ATT);
    float rx = ax * inv, ry = ay * inv;
    rx = (rx > 0.0f) ? rx : expm1f(rx);
    ry = (ry > 0.0f) ? ry : expm1f(ry);
    *reinterpret_cast<float2*>(&out[w * OUT_DIM + (lane << 1)]) = make_float2(rx, ry);
    if (lane == 0) g_cnt[w] = 0;   // self-clean for next run
}

// ---------------- launch ----------------
extern "C" void kernel_launch(void* const* d_in, const int* in_sizes, int n_in,
                              void* d_out, int out_size) {
    const float* X  = (const float*)d_in[0];
    const int*   ei = (const int*)d_in[1];    // int32 [2, E]
    const float* W  = (const float*)d_in[2];
    const float* a  = (const float*)d_in[3];
    float* out = (float*)d_out;

    int n = in_sizes[0] / IN_DIM;
    int e = in_sizes[1] / 2;

    gemm_kernel<<<(n + 31) / 32, 128>>>(X, W, a, n);
    hist_kernel<<<(e + 255) / 256, 256>>>(ei, e);
    scan_kernel<<<1, 1024>>>(n, e);
    reorder_kernel<<<(e + 255) / 256, 256>>>(ei, e);
    aggregate_kernel<<<(n * 32 + 255) / 256, 256>>>(out, n);
}

// round 10
// speedup vs baseline: 1.6962x; 1.6962x over previous
#include <cuda_runtime.h>
#include <math.h>

#define IN_DIM   128
#define OUT_DIM  64
#define N_MAX    50000
#define E_MAX    800000
#define ALPHA    0.2f
#define EPS_ATT  1e-10f

// ---------------- scratch (no allocations allowed) ----------------
// All scratch is self-cleaning: every kernel_launch leaves it zeroed where
// required, so graph replays are deterministic (zero-initialized at load).
__device__ __align__(16) float g_h[N_MAX * OUT_DIM];    // projected features
__device__ __align__(16) float g_out[N_MAX * OUT_DIM];  // unnormalized accum
__device__ float g_ssrc[N_MAX];            // h @ a[:64]
__device__ float g_stgt[N_MAX];            // h @ a[64:]
__device__ float g_esum[N_MAX];            // segment sum of exp

// ---------------- kernels ----------------

// GEMM: h = X @ W^T, fused with ssrc/stgt epilogue. Also zeroes g_esum for
// the scatter kernel that runs after it (replaces a dedicated init kernel).
// 128 threads/block, tile = 32 rows x 64 cols, each thread computes 4x4.
__global__ __launch_bounds__(128) void gemm_kernel(
    const float* X, const float* W, const float* a, int n)
{
    __shared__ float4 Xs[32 * 32];   // [row][kchunk]          16 KB
    __shared__ float4 Ws[64 * 32];   // [c][kchunk ^ swz]      32 KB

    int tid = threadIdx.x;
    for (int g = tid; g < 64 * 32; g += 128) {
        int c = g >> 5, kc = g & 31;
        Ws[(c << 5) | (kc ^ ((c >> 2) & 7))] = ((const float4*)W)[g];
    }
    int rowbase = blockIdx.x * 32;
    for (int g = tid; g < 32 * 32; g += 128) {
        int r = g >> 5, kc = g & 31;
        int row = rowbase + r;
        Xs[g] = (row < n) ? ((const float4*)X)[row * 32 + kc]
                          : make_float4(0.f, 0.f, 0.f, 0.f);
    }
    __syncthreads();

    int cg = tid & 15;
    int rg = tid >> 4;
    int c0 = cg << 2;
    int r0 = rg << 2;
    int swz = cg & 7;

    float acc[4][4] = {};
#pragma unroll 4
    for (int kc = 0; kc < 32; kc++) {
        float4 xv[4], wv[4];
#pragma unroll
        for (int j = 0; j < 4; j++)  xv[j] = Xs[((r0 + j) << 5) | kc];
#pragma unroll
        for (int jj = 0; jj < 4; jj++) wv[jj] = Ws[((c0 + jj) << 5) | (kc ^ swz)];
#pragma unroll
        for (int j = 0; j < 4; j++)
#pragma unroll
            for (int jj = 0; jj < 4; jj++)
                acc[j][jj] += xv[j].x * wv[jj].x + xv[j].y * wv[jj].y
                            + xv[j].z * wv[jj].z + xv[j].w * wv[jj].w;
    }

    float4 alo = ((const float4*)a)[cg];
    float4 ahi = ((const float4*)a)[16 + cg];

#pragma unroll
    for (int j = 0; j < 4; j++) {
        int row = rowbase + r0 + j;
        if (row < n) {
            float4 hv = make_float4(acc[j][0], acc[j][1], acc[j][2], acc[j][3]);
            *reinterpret_cast<float4*>(&g_h[row * OUT_DIM + c0]) = hv;
        }
        float p1 = acc[j][0]*alo.x + acc[j][1]*alo.y + acc[j][2]*alo.z + acc[j][3]*alo.w;
        float p2 = acc[j][0]*ahi.x + acc[j][1]*ahi.y + acc[j][2]*ahi.z + acc[j][3]*ahi.w;
#pragma unroll
        for (int off = 8; off; off >>= 1) {
            p1 += __shfl_down_sync(0xffffffffu, p1, off);
            p2 += __shfl_down_sync(0xffffffffu, p2, off);
        }
        if (cg == 0) {
            int row2 = rowbase + r0 + j;
            if (row2 < n) {
                g_ssrc[row2] = p1;
                g_stgt[row2] = p2;
                g_esum[row2] = 0.0f;   // pre-zero for scatter (runs after us)
            }
        }
    }
}

// Fused edge pass: score -> leaky_relu -> exp -> scatter UNNORMALIZED
// ex*h[src] into g_out and ex into g_esum. Softmax normalization commutes
// with the segment sum, so dividing by (esum+eps) afterwards is exact.
// 16 threads per edge; exp computed once (lane q==0) and shfl-broadcast.
// No max-subtraction: scores bounded ~[-20,20] for this input distribution,
// fp32 exp is safe and the softmax ratio is mathematically identical.
__global__ void fused_scatter_kernel(const int* ei, int e) {
    int idx = blockIdx.x * blockDim.x + threadIdx.x;
    int edge = idx >> 4;
    int q    = idx & 15;
    bool valid = edge < e;
    int s = 0, t = 0;
    if (valid) { s = ei[edge]; t = ei[e + edge]; }
    float ex = 0.0f;
    if (valid && q == 0) {
        float v = g_ssrc[s] + g_stgt[t];
        v = (v > 0.0f) ? v : ALPHA * v;
        ex = __expf(v);
        atomicAdd(&g_esum[t], ex);
    }
    ex = __shfl_sync(0xffffffffu, ex, (threadIdx.x & 31) & 16);
    if (!valid) return;

    const float4 hv = *reinterpret_cast<const float4*>(&g_h[s * OUT_DIM + (q << 2)]);
    float vx = hv.x * ex, vy = hv.y * ex, vz = hv.z * ex, vw = hv.w * ex;
    unsigned long long gp =
        (unsigned long long)__cvta_generic_to_global(&g_out[t * OUT_DIM + (q << 2)]);
    asm volatile("red.global.add.v4.f32 [%0], {%1, %2, %3, %4};"
                 :: "l"(gp), "f"(vx), "f"(vy), "f"(vz), "f"(vw) : "memory");
}

// Normalize + ELU, float4-vectorized; re-zeroes g_out (same elements this
// thread read — race-free) so the next replay starts clean.
__global__ void elu_kernel(float* out, int tot4) {
    int i = blockIdx.x * blockDim.x + threadIdx.x;
    if (i >= tot4) return;
    float4* go = reinterpret_cast<float4*>(g_out);
    float4 v = go[i];
    float inv = __fdividef(1.0f, g_esum[i >> 4] + EPS_ATT);
    float rx = v.x * inv, ry = v.y * inv, rz = v.z * inv, rw = v.w * inv;
    rx = (rx > 0.0f) ? rx : expm1f(rx);
    ry = (ry > 0.0f) ? ry : expm1f(ry);
    rz = (rz > 0.0f) ? rz : expm1f(rz);
    rw = (rw > 0.0f) ? rw : expm1f(rw);
    reinterpret_cast<float4*>(out)[i] = make_float4(rx, ry, rz, rw);
    go[i] = make_float4(0.f, 0.f, 0.f, 0.f);   // self-clean for next replay
}

// ---------------- launch ----------------
extern "C" void kernel_launch(void* const* d_in, const int* in_sizes, int n_in,
                              void* d_out, int out_size) {
    const float* X  = (const float*)d_in[0];
    const int*   ei = (const int*)d_in[1];    // int32 [2, E]
    const float* W  = (const float*)d_in[2];
    const float* a  = (const float*)d_in[3];
    float* out = (float*)d_out;

    int n = in_sizes[0] / IN_DIM;
    int e = in_sizes[1] / 2;
    int tot4 = n * OUT_DIM / 4;

    gemm_kernel<<<(n + 31) / 32, 128>>>(X, W, a, n);
    long long th = (long long)e * 16;
    fused_scatter_kernel<<<(int)((th + 255) / 256), 256>>>(ei, e);
    elu_kernel<<<(tot4 + 255) / 256, 256>>>(out, tot4);
}

// round 11
// speedup vs baseline: 1.8668x; 1.1005x over previous
#include <cuda_runtime.h>
#include <math.h>

#define IN_DIM   128
#define OUT_DIM  64
#define N_MAX    50000
#define E_MAX    800000
#define ALPHA    0.2f
#define EPS_ATT  1e-10f

typedef unsigned long long u64;

// packed dual-lane FMA: acc.{lo,hi} += a.{lo,hi} * b.{lo,hi}
#define FMA2(acc, va, vb) \
    asm("fma.rn.f32x2 %0, %1, %2, %0;" : "+l"(acc) : "l"(va), "l"(vb))

// ---------------- scratch (no allocations allowed) ----------------
// Self-cleaning across replays (graph-deterministic).
__device__ __align__(16) float g_h[N_MAX * OUT_DIM];    // projected features
__device__ __align__(16) float g_out[N_MAX * OUT_DIM];  // unnormalized accum
__device__ float g_ssrc[N_MAX];            // h @ a[:64]
__device__ float g_stgt[N_MAX];            // h @ a[64:]
__device__ float g_esum[N_MAX];            // segment sum of exp

// ---------------- kernels ----------------

// GEMM: h = X @ W^T fused with ssrc/stgt epilogue + g_esum zeroing.
// 256 threads/block, tile 64 rows x 64 cols, 4x4 per thread.
// Accumulators are f32x2 pairs over the k dimension (even/odd k lanes),
// so both FMA operands are natural 16B-load register pairs -> FFMA2 with
// zero packing MOVs. Horizontal add at the end.
__global__ __launch_bounds__(256) void gemm_kernel(
    const float* X, const float* W, const float* a, int n)
{
    __shared__ ulonglong2 Xs[64 * 32];   // 32 KB  [row][kchunk]
    __shared__ ulonglong2 Ws[64 * 32];   // 32 KB  [c][kchunk ^ swz]

    int tid = threadIdx.x;
    for (int g = tid; g < 64 * 32; g += 256) {
        int c = g >> 5, kc = g & 31;
        Ws[(c << 5) | (kc ^ ((c >> 2) & 7))] = ((const ulonglong2*)W)[g];
    }
    int rowbase = blockIdx.x * 64;
    for (int g = tid; g < 64 * 32; g += 256) {
        int r = g >> 5, kc = g & 31;
        int row = rowbase + r;
        Xs[g] = (row < n) ? ((const ulonglong2*)X)[row * 32 + kc]
                          : make_ulonglong2(0ull, 0ull);
    }
    __syncthreads();

    int cg = tid & 15;          // col group: c0 = cg*4
    int rg = tid >> 4;          // row group: r0 = rg*4  (16 groups)
    int c0 = cg << 2;
    int r0 = rg << 2;
    int swz = cg & 7;

    u64 acc[4][4];              // f32x2 pairs (k-even lane, k-odd lane)
#pragma unroll
    for (int j = 0; j < 4; j++)
#pragma unroll
        for (int jj = 0; jj < 4; jj++) acc[j][jj] = 0ull;

#pragma unroll 4
    for (int kc = 0; kc < 32; kc++) {
        ulonglong2 xv[4], wv[4];
#pragma unroll
        for (int j = 0; j < 4; j++)  xv[j] = Xs[((r0 + j) << 5) | kc];
#pragma unroll
        for (int jj = 0; jj < 4; jj++) wv[jj] = Ws[((c0 + jj) << 5) | (kc ^ swz)];
#pragma unroll
        for (int j = 0; j < 4; j++)
#pragma unroll
            for (int jj = 0; jj < 4; jj++) {
                FMA2(acc[j][jj], xv[j].x, wv[jj].x);   // k+0, k+1
                FMA2(acc[j][jj], xv[j].y, wv[jj].y);   // k+2, k+3
            }
    }

    // horizontal add of the two k-lanes
    float val[4][4];
#pragma unroll
    for (int j = 0; j < 4; j++)
#pragma unroll
        for (int jj = 0; jj < 4; jj++) {
            float2 f = *reinterpret_cast<float2*>(&acc[j][jj]);
            val[j][jj] = f.x + f.y;
        }

    float4 alo = ((const float4*)a)[cg];
    float4 ahi = ((const float4*)a)[16 + cg];

#pragma unroll
    for (int j = 0; j < 4; j++) {
        int row = rowbase + r0 + j;
        if (row < n) {
            float4 hv = make_float4(val[j][0], val[j][1], val[j][2], val[j][3]);
            *reinterpret_cast<float4*>(&g_h[row * OUT_DIM + c0]) = hv;
        }
        float p1 = val[j][0]*alo.x + val[j][1]*alo.y + val[j][2]*alo.z + val[j][3]*alo.w;
        float p2 = val[j][0]*ahi.x + val[j][1]*ahi.y + val[j][2]*ahi.z + val[j][3]*ahi.w;
        // reduce across the 16 col-groups (each half-warp is one row set)
#pragma unroll
        for (int off = 8; off; off >>= 1) {
            p1 += __shfl_down_sync(0xffffffffu, p1, off, 16);
            p2 += __shfl_down_sync(0xffffffffu, p2, off, 16);
        }
        if (cg == 0 && row < n) {
            g_ssrc[row] = p1;
            g_stgt[row] = p2;
            g_esum[row] = 0.0f;     // pre-zero for scatter (runs after us)
        }
    }
}

// Fused edge pass: score -> leaky_relu -> exp -> scatter UNNORMALIZED
// ex*h[src] into g_out and ex into g_esum. Normalization commutes with the
// segment sum, so dividing by (esum+eps) afterwards is exact.
// 16 threads per edge; exp computed once (q==0) and shfl-broadcast.
// No max-subtraction: scores bounded ~[-20,20] here; fp32 exp safe,
// softmax ratio mathematically identical.
__global__ void fused_scatter_kernel(const int* ei, int e) {
    int idx = blockIdx.x * blockDim.x + threadIdx.x;
    int edge = idx >> 4;
    int q    = idx & 15;
    bool valid = edge < e;
    int s = 0, t = 0;
    if (valid) { s = ei[edge]; t = ei[e + edge]; }
    float ex = 0.0f;
    if (valid && q == 0) {
        float v = g_ssrc[s] + g_stgt[t];
        v = (v > 0.0f) ? v : ALPHA * v;
        ex = __expf(v);
        atomicAdd(&g_esum[t], ex);
    }
    ex = __shfl_sync(0xffffffffu, ex, (threadIdx.x & 31) & 16);
    if (!valid) return;

    const float4 hv = *reinterpret_cast<const float4*>(&g_h[s * OUT_DIM + (q << 2)]);
    float vx = hv.x * ex, vy = hv.y * ex, vz = hv.z * ex, vw = hv.w * ex;
    unsigned long long gp =
        (unsigned long long)__cvta_generic_to_global(&g_out[t * OUT_DIM + (q << 2)]);
    asm volatile("red.global.add.v4.f32 [%0], {%1, %2, %3, %4};"
                 :: "l"(gp), "f"(vx), "f"(vy), "f"(vz), "f"(vw) : "memory");
}

// Normalize + ELU, float4-vectorized; re-zeroes g_out for the next replay.
__global__ void elu_kernel(float* out, int tot4) {
    int i = blockIdx.x * blockDim.x + threadIdx.x;
    if (i >= tot4) return;
    float4* go = reinterpret_cast<float4*>(g_out);
    float4 v = go[i];
    float inv = __fdividef(1.0f, g_esum[i >> 4] + EPS_ATT);
    float rx = v.x * inv, ry = v.y * inv, rz = v.z * inv, rw = v.w * inv;
    rx = (rx > 0.0f) ? rx : expm1f(rx);
    ry = (ry > 0.0f) ? ry : expm1f(ry);
    rz = (rz > 0.0f) ? rz : expm1f(rz);
    rw = (rw > 0.0f) ? rw : expm1f(rw);
    reinterpret_cast<float4*>(out)[i] = make_float4(rx, ry, rz, rw);
    go[i] = make_float4(0.f, 0.f, 0.f, 0.f);   // self-clean for next replay
}

// ---------------- launch ----------------
extern "C" void kernel_launch(void* const* d_in, const int* in_sizes, int n_in,
                              void* d_out, int out_size) {
    const float* X  = (const float*)d_in[0];
    const int*   ei = (const int*)d_in[1];    // int32 [2, E]
    const float* W  = (const float*)d_in[2];
    const float* a  = (const float*)d_in[3];
    float* out = (float*)d_out;

    int n = in_sizes[0] / IN_DIM;
    int e = in_sizes[1] / 2;
    int tot4 = n * OUT_DIM / 4;

    gemm_kernel<<<(n + 63) / 64, 256>>>(X, W, a, n);
    long long th = (long long)e * 16;
    fused_scatter_kernel<<<(int)((th + 255) / 256), 256>>>(ei, e);
    elu_kernel<<<(tot4 + 255) / 256, 256>>>(out, tot4);
}

// round 12
// speedup vs baseline: 1.8971x; 1.0162x over previous
#include <cuda_runtime.h>
#include <math.h>

#define IN_DIM   128
#define OUT_DIM  64
#define N_MAX    50000
#define E_MAX    800000
#define ALPHA    0.2f
#define EPS_ATT  1e-10f
#define GEMM_GRID 444   // 3 per SM x 148 SMs

typedef unsigned long long u64;

// packed dual-lane FMA: acc.{lo,hi} += a.{lo,hi} * b.{lo,hi}
#define FMA2(acc, va, vb) \
    asm("fma.rn.f32x2 %0, %1, %2, %0;" : "+l"(acc) : "l"(va), "l"(vb))

#define CP_ASYNC16(smem_u32, gptr) \
    asm volatile("cp.async.cg.shared.global [%0], [%1], 16;" \
                 :: "r"(smem_u32), "l"(gptr) : "memory")
#define CP_COMMIT()  asm volatile("cp.async.commit_group;" ::: "memory")
#define CP_WAIT(N)   asm volatile("cp.async.wait_group %0;" :: "n"(N) : "memory")

// ---------------- scratch (no allocations allowed) ----------------
// Self-cleaning across replays (graph-deterministic).
__device__ __align__(16) float g_h[N_MAX * OUT_DIM];    // projected features
__device__ __align__(16) float g_out[N_MAX * OUT_DIM];  // unnormalized accum
__device__ float g_ssrc[N_MAX];            // h @ a[:64]
__device__ float g_stgt[N_MAX];            // h @ a[64:]
__device__ float g_esum[N_MAX];            // segment sum of exp

// ---------------- kernels ----------------

// Persistent GEMM: h = X @ W^T fused with ssrc/stgt epilogue + esum zeroing.
// 444 blocks grid-stride over 64-row tiles. W (32KB smem) loaded ONCE per
// block. X streamed as 16KB k-halves, double-buffered with cp.async so the
// global->smem latency of half i+1 hides under compute of half i.
// Per-thread 4x4, accumulated as f32x2 pairs over k (FFMA2, no packing MOVs).
__global__ __launch_bounds__(256, 3) void gemm_kernel(
    const float* X, const float* W, const float* a, int n, int ntiles)
{
    __shared__ ulonglong2 Ws[64 * 32];        // 32 KB [c][kchunk ^ swz]
    __shared__ ulonglong2 Xs[2][64 * 16];     // 2 x 16 KB [row][kchunk-of-half]

    int tid = threadIdx.x;
    if (blockIdx.x >= ntiles) return;

    // W loaded once, swizzled so column-major reads are conflict-free
    for (int g = tid; g < 64 * 32; g += 256) {
        int c = g >> 5, kc = g & 31;
        Ws[(c << 5) | (kc ^ ((c >> 2) & 7))] = ((const ulonglong2*)W)[g];
    }

    int cg = tid & 15;          // col group: c0 = cg*4
    int rg = tid >> 4;          // row group: r0 = rg*4
    int c0 = cg << 2;
    int r0 = rg << 2;
    int swz = cg & 7;
    float4 alo = ((const float4*)a)[cg];
    float4 ahi = ((const float4*)a)[16 + cg];

    // prefetch a (tile, half) X slice into buffer b. 1024 chunks of 16B.
    auto prefetch = [&](int tile, int half, int b) {
        int tb = tile << 6;
        const char* base = (const char*)X;
#pragma unroll
        for (int g = tid; g < 64 * 16; g += 256) {
            int r = g >> 4, kc = g & 15;
            int row = tb + r; if (row >= n) row = n - 1;   // clamp (unused rows)
            unsigned su = (unsigned)__cvta_generic_to_shared(&Xs[b][g]);
            const char* gp = base + ((long long)row * 128 + half * 64 + kc * 4) * 4;
            CP_ASYNC16(su, gp);
        }
    };

    int tile = blockIdx.x, half = 0, buf = 0;
    prefetch(tile, 0, 0);
    CP_COMMIT();

    u64 acc[4][4];
#pragma unroll
    for (int j = 0; j < 4; j++)
#pragma unroll
        for (int jj = 0; jj < 4; jj++) acc[j][jj] = 0ull;

    for (;;) {
        int ntile = tile, nhalf = half + 1;
        if (nhalf == 2) { nhalf = 0; ntile = tile + GEMM_GRID; }
        bool hasNext = (ntile < ntiles);
        if (hasNext) { prefetch(ntile, nhalf, buf ^ 1); CP_COMMIT(); }
        if (hasNext) { CP_WAIT(1); } else { CP_WAIT(0); }
        __syncthreads();   // current half's data visible to all (incl. W on iter 0)

        // compute this k-half: 16 chunks of 4 k-values
#pragma unroll 4
        for (int kc = 0; kc < 16; kc++) {
            ulonglong2 xv[4], wv[4];
            int kch = (half << 4) | kc;
#pragma unroll
            for (int j = 0; j < 4; j++)  xv[j] = Xs[buf][((r0 + j) << 4) | kc];
#pragma unroll
            for (int jj = 0; jj < 4; jj++) wv[jj] = Ws[((c0 + jj) << 5) | (kch ^ swz)];
#pragma unroll
            for (int j = 0; j < 4; j++)
#pragma unroll
                for (int jj = 0; jj < 4; jj++) {
                    FMA2(acc[j][jj], xv[j].x, wv[jj].x);
                    FMA2(acc[j][jj], xv[j].y, wv[jj].y);
                }
        }

        if (half == 1) {
            // tile epilogue: horizontal add, store h, reduce attention partials
            float val[4][4];
#pragma unroll
            for (int j = 0; j < 4; j++)
#pragma unroll
                for (int jj = 0; jj < 4; jj++) {
                    float2 f = *reinterpret_cast<float2*>(&acc[j][jj]);
                    val[j][jj] = f.x + f.y;
                    acc[j][jj] = 0ull;      // reset for next tile
                }
            int rowbase = tile << 6;
#pragma unroll
            for (int j = 0; j < 4; j++) {
                int row = rowbase + r0 + j;
                if (row < n) {
                    float4 hv = make_float4(val[j][0], val[j][1], val[j][2], val[j][3]);
                    *reinterpret_cast<float4*>(&g_h[row * OUT_DIM + c0]) = hv;
                }
                float p1 = val[j][0]*alo.x + val[j][1]*alo.y + val[j][2]*alo.z + val[j][3]*alo.w;
                float p2 = val[j][0]*ahi.x + val[j][1]*ahi.y + val[j][2]*ahi.z + val[j][3]*ahi.w;
#pragma unroll
                for (int off = 8; off; off >>= 1) {
                    p1 += __shfl_down_sync(0xffffffffu, p1, off, 16);
                    p2 += __shfl_down_sync(0xffffffffu, p2, off, 16);
                }
                if (cg == 0 && row < n) {
                    g_ssrc[row] = p1;
                    g_stgt[row] = p2;
                    g_esum[row] = 0.0f;   // pre-zero for scatter
                }
            }
        }

        __syncthreads();   // WAR: all warps done with Xs[buf] before its reuse
        if (!hasNext) break;
        buf ^= 1; half = nhalf; tile = ntile;
    }
}

// Fused edge pass: score -> leaky_relu -> exp -> scatter UNNORMALIZED
// ex*h[src] into g_out and ex into g_esum. Normalization commutes with the
// segment sum, so dividing by (esum+eps) afterwards is exact.
// 16 threads per edge; exp computed once (q==0) and shfl-broadcast.
// No max-subtraction: scores bounded ~[-20,20] here; fp32 exp safe,
// softmax ratio mathematically identical.
__global__ void fused_scatter_kernel(const int* ei, int e) {
    int idx = blockIdx.x * blockDim.x + threadIdx.x;
    int edge = idx >> 4;
    int q    = idx & 15;
    bool valid = edge < e;
    int s = 0, t = 0;
    if (valid) { s = ei[edge]; t = ei[e + edge]; }
    float ex = 0.0f;
    if (valid && q == 0) {
        float v = g_ssrc[s] + g_stgt[t];
        v = (v > 0.0f) ? v : ALPHA * v;
        ex = __expf(v);
        atomicAdd(&g_esum[t], ex);
    }
    ex = __shfl_sync(0xffffffffu, ex, (threadIdx.x & 31) & 16);
    if (!valid) return;

    const float4 hv = *reinterpret_cast<const float4*>(&g_h[s * OUT_DIM + (q << 2)]);
    float vx = hv.x * ex, vy = hv.y * ex, vz = hv.z * ex, vw = hv.w * ex;
    unsigned long long gp =
        (unsigned long long)__cvta_generic_to_global(&g_out[t * OUT_DIM + (q << 2)]);
    asm volatile("red.global.add.v4.f32 [%0], {%1, %2, %3, %4};"
                 :: "l"(gp), "f"(vx), "f"(vy), "f"(vz), "f"(vw) : "memory");
}

// Normalize + ELU, float4-vectorized; re-zeroes g_out for the next replay.
__global__ void elu_kernel(float* out, int tot4) {
    int i = blockIdx.x * blockDim.x + threadIdx.x;
    if (i >= tot4) return;
    float4* go = reinterpret_cast<float4*>(g_out);
    float4 v = go[i];
    float inv = __fdividef(1.0f, g_esum[i >> 4] + EPS_ATT);
    float rx = v.x * inv, ry = v.y * inv, rz = v.z * inv, rw = v.w * inv;
    rx = (rx > 0.0f) ? rx : expm1f(rx);
    ry = (ry > 0.0f) ? ry : expm1f(ry);
    rz = (rz > 0.0f) ? rz : expm1f(rz);
    rw = (rw > 0.0f) ? rw : expm1f(rw);
    reinterpret_cast<float4*>(out)[i] = make_float4(rx, ry, rz, rw);
    go[i] = make_float4(0.f, 0.f, 0.f, 0.f);   // self-clean for next replay
}

// ---------------- launch ----------------
extern "C" void kernel_launch(void* const* d_in, const int* in_sizes, int n_in,
                              void* d_out, int out_size) {
    const float* X  = (const float*)d_in[0];
    const int*   ei = (const int*)d_in[1];    // int32 [2, E]
    const float* W  = (const float*)d_in[2];
    const float* a  = (const float*)d_in[3];
    float* out = (float*)d_out;

    int n = in_sizes[0] / IN_DIM;
    int e = in_sizes[1] / 2;
    int tot4 = n * OUT_DIM / 4;
    int ntiles = (n + 63) / 64;

    gemm_kernel<<<GEMM_GRID, 256>>>(X, W, a, n, ntiles);
    long long th = (long long)e * 16;
    fused_scatter_kernel<<<(int)((th + 255) / 256), 256>>>(ei, e);
    elu_kernel<<<(tot4 + 255) / 256, 256>>>(out, tot4);
}

// round 13
// speedup vs baseline: 1.9555x; 1.0308x over previous
#include <cuda_runtime.h>
#include <math.h>

#define IN_DIM   128
#define OUT_DIM  64
#define N_MAX    50000
#define E_MAX    800000
#define ALPHA    0.2f
#define EPS_ATT  1e-10f
#define GEMM_GRID 444   // 3 per SM x 148 SMs

typedef unsigned long long u64;

// packed dual-lane FMA: acc.{lo,hi} += a.{lo,hi} * b.{lo,hi}
#define FMA2(acc, va, vb) \
    asm("fma.rn.f32x2 %0, %1, %2, %0;" : "+l"(acc) : "l"(va), "l"(vb))

#define CP_ASYNC16(smem_u32, gptr) \
    asm volatile("cp.async.cg.shared.global [%0], [%1], 16;" \
                 :: "r"(smem_u32), "l"(gptr) : "memory")
#define CP_COMMIT()  asm volatile("cp.async.commit_group;" ::: "memory")
#define CP_WAIT(N)   asm volatile("cp.async.wait_group %0;" :: "n"(N) : "memory")

// ---------------- scratch (no allocations allowed) ----------------
// Self-cleaning across replays (graph-deterministic).
__device__ __align__(16) float g_h[N_MAX * OUT_DIM];    // projected features
__device__ __align__(16) float g_out[N_MAX * OUT_DIM];  // unnormalized accum
__device__ float g_ssrc[N_MAX];            // h @ a[:64]
__device__ float g_stgt[N_MAX];            // h @ a[64:]
__device__ float g_esum[N_MAX];            // segment sum of exp

// ---------------- kernels ----------------

// Persistent GEMM: h = X @ W^T fused with ssrc/stgt epilogue + esum zeroing.
// 444 blocks (one full wave) over 64-row tiles. W loaded ONCE per block.
// X streamed as 16KB k-halves, double-buffered with cp.async.
// Per-thread 4x4, accumulated as f32x2 pairs over k (FFMA2).
__global__ __launch_bounds__(256, 3) void gemm_kernel(
    const float* X, const float* W, const float* a, int n, int ntiles)
{
    __shared__ ulonglong2 Ws[64 * 32];        // 32 KB [c][kchunk ^ swz]
    __shared__ ulonglong2 Xs[2][64 * 16];     // 2 x 16 KB

    int tid = threadIdx.x;
    if (blockIdx.x >= ntiles) return;

    for (int g = tid; g < 64 * 32; g += 256) {
        int c = g >> 5, kc = g & 31;
        Ws[(c << 5) | (kc ^ ((c >> 2) & 7))] = ((const ulonglong2*)W)[g];
    }

    int cg = tid & 15;
    int rg = tid >> 4;
    int c0 = cg << 2;
    int r0 = rg << 2;
    int swz = cg & 7;
    float4 alo = ((const float4*)a)[cg];
    float4 ahi = ((const float4*)a)[16 + cg];

    auto prefetch = [&](int tile, int half, int b) {
        int tb = tile << 6;
        const char* base = (const char*)X;
#pragma unroll
        for (int g = tid; g < 64 * 16; g += 256) {
            int r = g >> 4, kc = g & 15;
            int row = tb + r; if (row >= n) row = n - 1;
            unsigned su = (unsigned)__cvta_generic_to_shared(&Xs[b][g]);
            const char* gp = base + ((long long)row * 128 + half * 64 + kc * 4) * 4;
            CP_ASYNC16(su, gp);
        }
    };

    int tile = blockIdx.x, half = 0, buf = 0;
    prefetch(tile, 0, 0);
    CP_COMMIT();

    u64 acc[4][4];
#pragma unroll
    for (int j = 0; j < 4; j++)
#pragma unroll
        for (int jj = 0; jj < 4; jj++) acc[j][jj] = 0ull;

    for (;;) {
        int ntile = tile, nhalf = half + 1;
        if (nhalf == 2) { nhalf = 0; ntile = tile + GEMM_GRID; }
        bool hasNext = (ntile < ntiles);
        if (hasNext) { prefetch(ntile, nhalf, buf ^ 1); CP_COMMIT(); }
        if (hasNext) { CP_WAIT(1); } else { CP_WAIT(0); }
        __syncthreads();

#pragma unroll 4
        for (int kc = 0; kc < 16; kc++) {
            ulonglong2 xv[4], wv[4];
            int kch = (half << 4) | kc;
#pragma unroll
            for (int j = 0; j < 4; j++)  xv[j] = Xs[buf][((r0 + j) << 4) | kc];
#pragma unroll
            for (int jj = 0; jj < 4; jj++) wv[jj] = Ws[((c0 + jj) << 5) | (kch ^ swz)];
#pragma unroll
            for (int j = 0; j < 4; j++)
#pragma unroll
                for (int jj = 0; jj < 4; jj++) {
                    FMA2(acc[j][jj], xv[j].x, wv[jj].x);
                    FMA2(acc[j][jj], xv[j].y, wv[jj].y);
                }
        }

        if (half == 1) {
            float val[4][4];
#pragma unroll
            for (int j = 0; j < 4; j++)
#pragma unroll
                for (int jj = 0; jj < 4; jj++) {
                    float2 f = *reinterpret_cast<float2*>(&acc[j][jj]);
                    val[j][jj] = f.x + f.y;
                    acc[j][jj] = 0ull;
                }
            int rowbase = tile << 6;
#pragma unroll
            for (int j = 0; j < 4; j++) {
                int row = rowbase + r0 + j;
                if (row < n) {
                    float4 hv = make_float4(val[j][0], val[j][1], val[j][2], val[j][3]);
                    *reinterpret_cast<float4*>(&g_h[row * OUT_DIM + c0]) = hv;
                }
                float p1 = val[j][0]*alo.x + val[j][1]*alo.y + val[j][2]*alo.z + val[j][3]*alo.w;
                float p2 = val[j][0]*ahi.x + val[j][1]*ahi.y + val[j][2]*ahi.z + val[j][3]*ahi.w;
#pragma unroll
                for (int off = 8; off; off >>= 1) {
                    p1 += __shfl_down_sync(0xffffffffu, p1, off, 16);
                    p2 += __shfl_down_sync(0xffffffffu, p2, off, 16);
                }
                if (cg == 0 && row < n) {
                    g_ssrc[row] = p1;
                    g_stgt[row] = p2;
                    g_esum[row] = 0.0f;
                }
            }
        }

        __syncthreads();
        if (!hasNext) break;
        buf ^= 1; half = nhalf; tile = ntile;
    }
}

// Fused edge pass, 2 edges per 16-lane group for ILP:
// lanes q=0,q=1 compute the two exps IN PARALLEL (+ esum atomics), both
// shfl-broadcast; two independent gathers (MLP=2) + two RED.128 per thread.
// Scatter is UNNORMALIZED ex*h[src]; normalization commutes with the
// segment sum and is applied in elu. No max-subtraction: scores bounded
// ~[-20,20] here, fp32 exp safe, softmax ratio mathematically identical.
__global__ void fused_scatter_kernel(const int* ei, int e) {
    int idx = blockIdx.x * blockDim.x + threadIdx.x;
    int grp = idx >> 4;
    int q   = idx & 15;
    int e0  = grp << 1;
    if (e0 >= e) return;
    int e1  = e0 + 1;
    bool has1 = (e1 < e);

    int s0 = ei[e0], t0 = ei[e + e0];
    int s1 = s0, t1 = t0;
    if (has1) { s1 = ei[e1]; t1 = ei[e + e1]; }

    float ex0 = 0.0f, ex1 = 0.0f;
    if (q == 0) {
        float v = g_ssrc[s0] + g_stgt[t0];
        v = (v > 0.0f) ? v : ALPHA * v;
        ex0 = __expf(v);
        atomicAdd(&g_esum[t0], ex0);
    } else if (q == 1 && has1) {
        float v = g_ssrc[s1] + g_stgt[t1];
        v = (v > 0.0f) ? v : ALPHA * v;
        ex1 = __expf(v);
        atomicAdd(&g_esum[t1], ex1);
    }
    int base = threadIdx.x & 16;   // 16-lane group base within warp
    ex0 = __shfl_sync(0xffffffffu, ex0, base + 0);
    ex1 = __shfl_sync(0xffffffffu, ex1, base + 1);

    const float4 h0 = *reinterpret_cast<const float4*>(&g_h[s0 * OUT_DIM + (q << 2)]);
    const float4 h1 = *reinterpret_cast<const float4*>(&g_h[s1 * OUT_DIM + (q << 2)]);

    unsigned long long gp0 =
        (unsigned long long)__cvta_generic_to_global(&g_out[t0 * OUT_DIM + (q << 2)]);
    asm volatile("red.global.add.v4.f32 [%0], {%1, %2, %3, %4};"
                 :: "l"(gp0), "f"(h0.x * ex0), "f"(h0.y * ex0),
                    "f"(h0.z * ex0), "f"(h0.w * ex0) : "memory");
    if (has1) {
        unsigned long long gp1 =
            (unsigned long long)__cvta_generic_to_global(&g_out[t1 * OUT_DIM + (q << 2)]);
        asm volatile("red.global.add.v4.f32 [%0], {%1, %2, %3, %4};"
                     :: "l"(gp1), "f"(h1.x * ex1), "f"(h1.y * ex1),
                        "f"(h1.z * ex1), "f"(h1.w * ex1) : "memory");
    }
}

// Normalize + ELU, float4-vectorized; re-zeroes g_out for the next replay.
__global__ void elu_kernel(float* out, int tot4) {
    int i = blockIdx.x * blockDim.x + threadIdx.x;
    if (i >= tot4) return;
    float4* go = reinterpret_cast<float4*>(g_out);
    float4 v = go[i];
    float inv = __fdividef(1.0f, g_esum[i >> 4] + EPS_ATT);
    float rx = v.x * inv, ry = v.y * inv, rz = v.z * inv, rw = v.w * inv;
    rx = (rx > 0.0f) ? rx : expm1f(rx);
    ry = (ry > 0.0f) ? ry : expm1f(ry);
    rz = (rz > 0.0f) ? rz : expm1f(rz);
    rw = (rw > 0.0f) ? rw : expm1f(rw);
    reinterpret_cast<float4*>(out)[i] = make_float4(rx, ry, rz, rw);
    go[i] = make_float4(0.f, 0.f, 0.f, 0.f);   // self-clean for next replay
}

// ---------------- launch ----------------
extern "C" void kernel_launch(void* const* d_in, const int* in_sizes, int n_in,
                              void* d_out, int out_size) {
    const float* X  = (const float*)d_in[0];
    const int*   ei = (const int*)d_in[1];    // int32 [2, E]
    const float* W  = (const float*)d_in[2];
    const float* a  = (const float*)d_in[3];
    float* out = (float*)d_out;

    int n = in_sizes[0] / IN_DIM;
    int e = in_sizes[1] / 2;
    int tot4 = n * OUT_DIM / 4;
    int ntiles = (n + 63) / 64;

    gemm_kernel<<<GEMM_GRID, 256>>>(X, W, a, n, ntiles);
    long long groups = (e + 1) / 2;
    long long th = groups * 16;
    fused_scatter_kernel<<<(int)((th + 255) / 256), 256>>>(ei, e);
    elu_kernel<<<(tot4 + 255) / 256, 256>>>(out, tot4);
}

// round 15
// speedup vs baseline: 1.9903x; 1.0178x over previous
#include <cuda_runtime.h>
#include <math.h>

#define IN_DIM   128
#define OUT_DIM  64
#define N_MAX    50000
#define E_MAX    800000
#define ALPHA    0.2f
#define EPS_ATT  1e-10f
#define GEMM_GRID 296   // 2 per SM x 148 SMs

typedef unsigned long long u64;

// packed dual-lane FMA: acc.{lo,hi} += a.{lo,hi} * b.{lo,hi}
#define FMA2(acc, va, vb) \
    asm("fma.rn.f32x2 %0, %1, %2, %0;" : "+l"(acc) : "l"(va), "l"(vb))

#define CP_ASYNC16(smem_u32, gptr) \
    asm volatile("cp.async.cg.shared.global [%0], [%1], 16;" \
                 :: "r"(smem_u32), "l"(gptr) : "memory")
#define CP_COMMIT()  asm volatile("cp.async.commit_group;" ::: "memory")
#define CP_WAIT(N)   asm volatile("cp.async.wait_group %0;" :: "n"(N) : "memory")

// ---------------- scratch (no allocations allowed) ----------------
// Self-cleaning across replays (graph-deterministic).
__device__ __align__(16) float g_h[N_MAX * OUT_DIM];    // projected features
__device__ __align__(16) float g_out[N_MAX * OUT_DIM];  // unnormalized accum
__device__ float g_ssrc[N_MAX];            // h @ a[:64]
__device__ float g_stgt[N_MAX];            // h @ a[64:]
__device__ float g_esum[N_MAX];            // segment sum of exp

// ---------------- kernels ----------------

// Persistent GEMM: h = X @ W^T fused with ssrc/stgt epilogue + esum zeroing.
// 296 blocks (2/SM, 32 warps/SM) over 128-row tiles. W loaded ONCE per
// block (32KB). X streamed as 32KB k-halves, double-buffered with cp.async.
// Per-thread 4x4, accumulated as f32x2 pairs over k (FFMA2). smem = 96KB.
__global__ __launch_bounds__(512, 2) void gemm_kernel(
    const float* X, const float* W, const float* a, int n, int ntiles)
{
    __shared__ ulonglong2 Ws[64 * 32];        // 32 KB [c][kchunk ^ swz]
    __shared__ ulonglong2 Xs[2][128 * 16];    // 2 x 32 KB [row][kchunk-of-half]

    int tid = threadIdx.x;
    if (blockIdx.x >= ntiles) return;

    for (int g = tid; g < 64 * 32; g += 512) {
        int c = g >> 5, kc = g & 31;
        Ws[(c << 5) | (kc ^ ((c >> 2) & 7))] = ((const ulonglong2*)W)[g];
    }

    int cg = tid & 15;          // col group: c0 = cg*4
    int rg = tid >> 4;          // row group: r0 = rg*4 (32 groups -> 128 rows)
    int c0 = cg << 2;
    int r0 = rg << 2;
    int swz = cg & 7;
    float4 alo = ((const float4*)a)[cg];
    float4 ahi = ((const float4*)a)[16 + cg];

    // prefetch a (tile, half) X slice: 128 rows x 16 chunks of 16B
    auto prefetch = [&](int tile, int half, int b) {
        int tb = tile << 7;
        const char* base = (const char*)X;
#pragma unroll
        for (int g = tid; g < 128 * 16; g += 512) {
            int r = g >> 4, kc = g & 15;
            int row = tb + r; if (row >= n) row = n - 1;   // clamp (rows unused)
            unsigned su = (unsigned)__cvta_generic_to_shared(&Xs[b][g]);
            const char* gp = base + ((long long)row * 128 + half * 64 + kc * 4) * 4;
            CP_ASYNC16(su, gp);
        }
    };

    int tile = blockIdx.x, half = 0, buf = 0;
    prefetch(tile, 0, 0);
    CP_COMMIT();

    u64 acc[4][4];
#pragma unroll
    for (int j = 0; j < 4; j++)
#pragma unroll
        for (int jj = 0; jj < 4; jj++) acc[j][jj] = 0ull;

    for (;;) {
        int ntile = tile, nhalf = half + 1;
        if (nhalf == 2) { nhalf = 0; ntile = tile + GEMM_GRID; }
        bool hasNext = (ntile < ntiles);
        if (hasNext) { prefetch(ntile, nhalf, buf ^ 1); CP_COMMIT(); }
        if (hasNext) { CP_WAIT(1); } else { CP_WAIT(0); }
        __syncthreads();   // current half visible (incl. W on iter 0)

#pragma unroll 4
        for (int kc = 0; kc < 16; kc++) {
            ulonglong2 xv[4], wv[4];
            int kch = (half << 4) | kc;
#pragma unroll
            for (int j = 0; j < 4; j++)  xv[j] = Xs[buf][((r0 + j) << 4) | kc];
#pragma unroll
            for (int jj = 0; jj < 4; jj++) wv[jj] = Ws[((c0 + jj) << 5) | (kch ^ swz)];
#pragma unroll
            for (int j = 0; j < 4; j++)
#pragma unroll
                for (int jj = 0; jj < 4; jj++) {
                    FMA2(acc[j][jj], xv[j].x, wv[jj].x);
                    FMA2(acc[j][jj], xv[j].y, wv[jj].y);
                }
        }

        if (half == 1) {
            float val[4][4];
#pragma unroll
            for (int j = 0; j < 4; j++)
#pragma unroll
                for (int jj = 0; jj < 4; jj++) {
                    float2 f = *reinterpret_cast<float2*>(&acc[j][jj]);
                    val[j][jj] = f.x + f.y;
                    acc[j][jj] = 0ull;
                }
            int rowbase = tile << 7;
#pragma unroll
            for (int j = 0; j < 4; j++) {
                int row = rowbase + r0 + j;
                if (row < n) {
                    float4 hv = make_float4(val[j][0], val[j][1], val[j][2], val[j][3]);
                    *reinterpret_cast<float4*>(&g_h[row * OUT_DIM + c0]) = hv;
                }
                float p1 = val[j][0]*alo.x + val[j][1]*alo.y + val[j][2]*alo.z + val[j][3]*alo.w;
                float p2 = val[j][0]*ahi.x + val[j][1]*ahi.y + val[j][2]*ahi.z + val[j][3]*ahi.w;
#pragma unroll
                for (int off = 8; off; off >>= 1) {
                    p1 += __shfl_down_sync(0xffffffffu, p1, off, 16);
                    p2 += __shfl_down_sync(0xffffffffu, p2, off, 16);
                }
                if (cg == 0 && row < n) {
                    g_ssrc[row] = p1;
                    g_stgt[row] = p2;
                    g_esum[row] = 0.0f;   // pre-zero for scatter
                }
            }
        }

        __syncthreads();   // WAR on Xs[buf]
        if (!hasNext) break;
        buf ^= 1; half = nhalf; tile = ntile;
    }
}

// Fused edge pass, 2 edges per 16-lane group:
// lanes q=0,q=1 compute the two exps in parallel (+ esum atomics), both
// shfl-broadcast; two independent gathers (MLP=2) + two RED.128 per thread.
// Scatter is UNNORMALIZED ex*h[src]; normalization commutes with the segment
// sum and is applied in elu. No max-subtraction: scores bounded ~[-20,20]
// here, fp32 exp safe, softmax ratio mathematically identical.
__global__ void fused_scatter_kernel(const int* ei, int e) {
    int idx = blockIdx.x * blockDim.x + threadIdx.x;
    int grp = idx >> 4;
    int q   = idx & 15;
    int e0  = grp << 1;
    if (e0 >= e) return;
    int e1  = e0 + 1;
    bool has1 = (e1 < e);

    int s0 = ei[e0], t0 = ei[e + e0];
    int s1 = s0, t1 = t0;
    if (has1) { s1 = ei[e1]; t1 = ei[e + e1]; }

    float ex0 = 0.0f, ex1 = 0.0f;
    if (q == 0) {
        float v = g_ssrc[s0] + g_stgt[t0];
        v = (v > 0.0f) ? v : ALPHA * v;
        ex0 = __expf(v);
        atomicAdd(&g_esum[t0], ex0);
    } else if (q == 1 && has1) {
        float v = g_ssrc[s1] + g_stgt[t1];
        v = (v > 0.0f) ? v : ALPHA * v;
        ex1 = __expf(v);
        atomicAdd(&g_esum[t1], ex1);
    }
    int base = threadIdx.x & 16;
    ex0 = __shfl_sync(0xffffffffu, ex0, base + 0);
    ex1 = __shfl_sync(0xffffffffu, ex1, base + 1);

    const float4 h0 = *reinterpret_cast<const float4*>(&g_h[s0 * OUT_DIM + (q << 2)]);
    const float4 h1 = *reinterpret_cast<const float4*>(&g_h[s1 * OUT_DIM + (q << 2)]);

    unsigned long long gp0 =
        (unsigned long long)__cvta_generic_to_global(&g_out[t0 * OUT_DIM + (q << 2)]);
    asm volatile("red.global.add.v4.f32 [%0], {%1, %2, %3, %4};"
                 :: "l"(gp0), "f"(h0.x * ex0), "f"(h0.y * ex0),
                    "f"(h0.z * ex0), "f"(h0.w * ex0) : "memory");
    if (has1) {
        unsigned long long gp1 =
            (unsigned long long)__cvta_generic_to_global(&g_out[t1 * OUT_DIM + (q << 2)]);
        asm volatile("red.global.add.v4.f32 [%0], {%1, %2, %3, %4};"
                     :: "l"(gp1), "f"(h1.x * ex1), "f"(h1.y * ex1),
                        "f"(h1.z * ex1), "f"(h1.w * ex1) : "memory");
    }
}

// Normalize + ELU, float4-vectorized; re-zeroes g_out for the next replay.
__global__ void elu_kernel(float* out, int tot4) {
    int i = blockIdx.x * blockDim.x + threadIdx.x;
    if (i >= tot4) return;
    float4* go = reinterpret_cast<float4*>(g_out);
    float4 v = go[i];
    float inv = __fdividef(1.0f, g_esum[i >> 4] + EPS_ATT);
    float rx = v.x * inv, ry = v.y * inv, rz = v.z * inv, rw = v.w * inv;
    rx = (rx > 0.0f) ? rx : expm1f(rx);
    ry = (ry > 0.0f) ? ry : expm1f(ry);
    rz = (rz > 0.0f) ? rz : expm1f(rz);
    rw = (rw > 0.0f) ? rw : expm1f(rw);
    reinterpret_cast<float4*>(out)[i] = make_float4(rx, ry, rz, rw);
    go[i] = make_float4(0.f, 0.f, 0.f, 0.f);   // self-clean for next replay
}

// ---------------- launch ----------------
extern "C" void kernel_launch(void* const* d_in, const int* in_sizes, int n_in,
                              void* d_out, int out_size) {
    const float* X  = (const float*)d_in[0];
    const int*   ei = (const int*)d_in[1];    // int32 [2, E]
    const float* W  = (const float*)d_in[2];
    const float* a  = (const float*)d_in[3];
    float* out = (float*)d_out;

    int n = in_sizes[0] / IN_DIM;
    int e = in_sizes[1] / 2;
    int tot4 = n * OUT_DIM / 4;
    int ntiles = (n + 127) / 128;

    gemm_kernel<<<GEMM_GRID, 512>>>(X, W, a, n, ntiles);
    long long groups = (e + 1) / 2;
    long long th = groups * 16;
    fused_scatter_kernel<<<(int)((th + 255) / 256), 256>>>(ei, e);
    elu_kernel<<<(tot4 + 255) / 256, 256>>>(out, tot4);
}